// round 16
// baseline (speedup 1.0000x reference)
#include <cuda_runtime.h>
#include <cuda_fp16.h>
#include <math.h>
#include <stdint.h>

#define HID   1024
#define EMBD  512
#define BATCH 64
#define SEQ   512
#define G4    4096
#define NBLK  128

// ===================== device scratch =====================
// W_hh fp16, m16n8k16 B-fragment order (single plane):
//   u32 idx = (((jj*64 + s)*4 + g)*32 + lane)*2 + khalf
__device__ uint32_t g_wfrag16[128 * 64 * 4 * 32 * 2];      // 4 MB
// W_ih fp16 B-fragment order (single plane):
//   u32 idx = ((ntile*32 + s)*32 + lane)*2 + khalf
__device__ uint32_t g_wihfrag[512 * 32 * 32 * 2];          // 4 MB
// emb rows in A-fragment order, fp16 single plane:
//   uint4 idx = (mtile*32 + s)*32 + lane
__device__ uint4    g_afrag[2048 * 32 * 32];               // 33 MB
// h in A-fragment order, fp16: part0 = hi, part1 = (h-hi)*2048; double buffered
__device__ uint32_t g_hfrag[2][64 * 4 * 32 * 8];           // 512 KB x2
__device__ float    g_hfin[BATCH * HID];
__device__ unsigned g_count;

__global__ void init_kernel() {
    if (blockIdx.x == 0 && threadIdx.x == 0) g_count = 0u;
}

// ===================== helpers =====================
// fast sigmoid: rcp(1 + 2^(-v*log2e)); abs error ~2^-22 (MUFU approx)
__device__ __forceinline__ float sigmf(float v) {
    float e, r;
    asm("ex2.approx.f32 %0, %1;" : "=f"(e) : "f"(-v * 1.4426950408889634f));
    asm("rcp.approx.f32 %0, %1;" : "=f"(r) : "f"(1.0f + e));
    return r;
}
// fast tanh: 1 - 2*rcp(2^(2x*log2e) + 1); abs error ~2^-22
__device__ __forceinline__ float tanhfast(float x) {
    float e, r;
    asm("ex2.approx.f32 %0, %1;" : "=f"(e) : "f"(x * 2.8853900817779268f));
    asm("rcp.approx.f32 %0, %1;" : "=f"(r) : "f"(e + 1.0f));
    return 1.0f - 2.0f * r;
}

__device__ __forceinline__ uint32_t pack_f16x2(float e0, float e1) {
    __half2 h = __floats2half2_rn(e0, e1);
    return *(uint32_t*)&h;
}
__device__ __forceinline__ float f16val(float v) {
    return __half2float(__float2half_rn(v));
}

#define MMA_F16(d, a, b0, b1) \
    asm volatile("mma.sync.aligned.m16n8k16.row.col.f32.f16.f16.f32 " \
        "{%0,%1,%2,%3}, {%4,%5,%6,%7}, {%8,%9}, {%0,%1,%2,%3};" \
        : "+f"((d)[0]), "+f"((d)[1]), "+f"((d)[2]), "+f"((d)[3]) \
        : "r"((a).x), "r"((a).y), "r"((a).z), "r"((a).w), "r"(b0), "r"(b1))

// ===================== W_hh -> fp16 fragment converter =====================
__global__ void wconv_kernel(const float* __restrict__ W_hh) {
    int id = blockIdx.x * blockDim.x + threadIdx.x;   // 4096*512 (n, k-pair)
    if (id >= 4096 * 512) return;
    int n  = id >> 9;
    int k  = (id & 511) * 2;
    float2 w = *(const float2*)(W_hh + (size_t)n * HID + k);

    int g  = n >> 10, jj = (n >> 3) & 127, ul = n & 7;
    int s  = k >> 4, tig = (k >> 1) & 3, khalf = (k >> 3) & 1;
    int lane = (ul << 2) | tig;
    uint32_t base = (uint32_t)((((jj * 64 + s) * 4 + g) * 32 + lane) * 2 + khalf);
    g_wfrag16[base] = pack_f16x2(w.x, w.y);
}

// ===================== W_ih -> fp16 fragment converter =====================
__global__ void wihconv_kernel(const float* __restrict__ W_ih) {
    int id = blockIdx.x * blockDim.x + threadIdx.x;   // 4096*256 k-pairs
    if (id >= 4096 * 256) return;
    int n  = id >> 8;
    int k  = (id & 255) * 2;
    float2 w = *(const float2*)(W_ih + (size_t)n * EMBD + k);

    int ntile = n >> 3, ul = n & 7;
    int s = k >> 4, tig = (k >> 1) & 3, khalf = (k >> 3) & 1;
    int lane = (ul << 2) | tig;
    uint32_t base = (uint32_t)(((ntile * 32 + s) * 32 + lane) * 2 + khalf);
    g_wihfrag[base] = pack_f16x2(w.x, w.y);
}

// ===================== embedding gather -> fp16 A fragments (1 plane) ==========
__global__ void gather_kernel(const int*   __restrict__ x,
                              const float* __restrict__ emb_table) {
    __shared__ int toks[16];
    const int mtile = blockIdx.x;
    const int tid = threadIdx.x;
    const int wid = tid >> 5;
    const int lid = tid & 31;

    if (tid < 16) {
        int m = mtile * 16 + tid;
        int t = m >> 6, b = m & 63;
        toks[tid] = x[b * SEQ + t];
    }
    __syncthreads();

    const int r0 = lid >> 2;
    const int c0 = (lid & 3) * 2;
    const int tok0 = toks[r0];
    const int tok1 = toks[r0 + 8];
    const float* e0 = emb_table + (size_t)tok0 * EMBD;
    const float* e1 = emb_table + (size_t)tok1 * EMBD;

#pragma unroll
    for (int q = 0; q < 4; q++) {
        int s = wid * 4 + q;
        int kb = s * 16;
        float2 v00 = (tok0 == 0) ? make_float2(0.f, 0.f) : *(const float2*)(e0 + kb + c0);
        float2 v01 = (tok0 == 0) ? make_float2(0.f, 0.f) : *(const float2*)(e0 + kb + c0 + 8);
        float2 v10 = (tok1 == 0) ? make_float2(0.f, 0.f) : *(const float2*)(e1 + kb + c0);
        float2 v11 = (tok1 == 0) ? make_float2(0.f, 0.f) : *(const float2*)(e1 + kb + c0 + 8);

        uint4 hi;
        hi.x = pack_f16x2(v00.x, v00.y);
        hi.y = pack_f16x2(v10.x, v10.y);
        hi.z = pack_f16x2(v01.x, v01.y);
        hi.w = pack_f16x2(v11.x, v11.y);

        g_afrag[((size_t)mtile * 32 + s) * 32 + lid] = hi;
    }
}

// ===================== grid barrier primitives =====================
__device__ __forceinline__ void grid_bar_full(unsigned target) {
    __syncthreads();
    if (threadIdx.x == 0) {
        asm volatile("red.release.gpu.global.add.u32 [%0], %1;"
                     :: "l"(&g_count), "r"(1u) : "memory");
        unsigned v;
        while (true) {
            asm volatile("ld.acquire.gpu.global.u32 %0, [%1];"
                         : "=r"(v) : "l"(&g_count) : "memory");
            if (v >= target * NBLK) break;
            __nanosleep(16);
        }
    }
    __syncthreads();
}

// ===================== fused x_proj warp-tile (validated round-13 mapping) =======
// Tile q = gate*4 + mtile: computes xs[buf][mtile*16 + a][gate*8 + ul]
//   = emb(t=tt) . W_ih + b_ih for this block's 8 columns of gate `gate`.
__device__ __forceinline__ void xproj_tile(int tt, int buf, int j, int q,
                                           int lid, float xs[2][64][36],
                                           const float* bihs) {
    const int g   = q >> 2;
    const int mtl = q & 3;
    const uint4* ab = g_afrag + ((size_t)(tt * 4 + mtl) * 32) * 32 + lid;
    const uint2* bb = ((const uint2*)g_wihfrag)
                    + ((size_t)(g * 128 + j) * 32) * 32 + lid;
    float ax[4] = {0.f, 0.f, 0.f, 0.f};
    uint4 Ar[4];
    uint2 Br[4];
#pragma unroll
    for (int p = 0; p < 3; p++) {
        Ar[p] = __ldg(ab + (size_t)p * 32);
        Br[p] = __ldg(bb + (size_t)p * 32);
    }
#pragma unroll
    for (int s = 0; s < 32; s++) {
        if (s < 29) {
            Ar[(s + 3) & 3] = __ldg(ab + (size_t)(s + 3) * 32);
            Br[(s + 3) & 3] = __ldg(bb + (size_t)(s + 3) * 32);
        }
        MMA_F16(ax, Ar[s & 3], Br[s & 3].x, Br[s & 3].y);
    }
    int a = lid >> 2, bq = lid & 3;
    int colb = g * 8 + bq * 2;
    float bi0 = bihs[colb], bi1 = bihs[colb + 1];
    *(float2*)&xs[buf][mtl * 16 + a][colb]     = make_float2(ax[0] + bi0, ax[1] + bi1);
    *(float2*)&xs[buf][mtl * 16 + a + 8][colb] = make_float2(ax[2] + bi0, ax[3] + bi1);
}

// ===================== persistent LSTM recurrence + shadow xproj ================
// Split-barrier pipeline: warps 0-3 (kh==0) do reduce+epilogue+arrive; warps 4-15
// compute x_proj[t+1] tiles in the same window (tensor pipe otherwise idle).
__global__ void __launch_bounds__(512, 1)
lstm_persistent(const float* __restrict__ b_hh, const float* __restrict__ b_ih) {
    __shared__ float xs[2][64][36];
    __shared__ float psum[3][4][16][32];
    __shared__ float bhs[32];
    __shared__ float bihs[32];

    const int j   = blockIdx.x;
    const int tid = threadIdx.x;
    const int wid = tid >> 5;
    const int lid = tid & 31;
    const int kh  = wid >> 2;              // K-quarter 0..3
    const int mt  = wid & 3;               // m-tile
    const int r0  = mt * 16 + (lid >> 2);
    const int tig = lid & 3;
    const int sj  = j >> 1;
    const int regbase = (j & 1) << 1;

    if (tid < 32) {
        int g = tid >> 3, ul = tid & 7;
        bhs[tid]  = b_hh[g * HID + j * 8 + ul];
        bihs[tid] = b_ih[g * HID + j * 8 + ul];
    }

    if (wid < 4) {
        uint32_t* hb = g_hfrag[0] + (((sj * 4 + wid) * 32 + lid) * 8);
#pragma unroll
        for (int mh = 0; mh < 2; mh++) {
            hb[regbase + mh]     = 0u;
            hb[4 + regbase + mh] = 0u;
        }
    }
    float creg[4];
#pragma unroll
    for (int q = 0; q < 4; q++) creg[q] = 0.0f;

    __syncthreads();           // bihs visible for prologue
    // prologue: x_proj[0] -> xs[0] (warps 4-15; 4-7 take two tiles)
    if (wid >= 4) {
        int q = wid - 4;
        xproj_tile(0, 0, j, q, lid, xs, bihs);
        if (wid < 8) xproj_tile(0, 0, j, q + 12, lid, xs, bihs);
    }

    grid_bar_full(1);          // h zeroed + xs[0] ready everywhere; counter = NBLK

    // B-fragment base for this warp's K-quarter (uint2; per-s stride 128, per-g 32)
    const uint2* wbase = ((const uint2*)g_wfrag16)
                       + ((size_t)j * 64 + kh * 16) * 128 + lid;

    for (int t = 0; t < SEQ; t++) {
        const int cb = t & 1, nb = cb ^ 1;

        // ===== PHASE 1: B prefetch (h-independent) =====
        uint2 Bb[2][4];
#pragma unroll
        for (int g = 0; g < 4; g++) Bb[0][g] = __ldg(wbase + g * 32);

        // ===== PHASE 2: wait for all blocks' h writes of step t-1 =====
        if (tid == 0) {
            const unsigned tgt = (unsigned)(t + 1) * NBLK;
            unsigned v;
            while (true) {
                asm volatile("ld.acquire.gpu.global.u32 %0, [%1];"
                             : "=r"(v) : "l"(&g_count) : "memory");
                if (v >= tgt) break;
                __nanosleep(16);
            }
        }
        __syncthreads();

        // ===== PHASE 3: K-quarter MMA loop (16 k-steps, 2 mma per g) =====
        const uint4* habase = ((const uint4*)g_hfrag[cb])
                            + ((size_t)(kh * 64 + mt)) * 64 + lid * 2;
        uint4 Ab[4][2];       // ring, fill distance 3
        float acc1[4][4], acc2[4][4];
#pragma unroll
        for (int g = 0; g < 4; g++)
#pragma unroll
            for (int c = 0; c < 4; c++) { acc1[g][c] = 0.0f; acc2[g][c] = 0.0f; }

#pragma unroll
        for (int p = 0; p < 3; p++) {
            const uint4* ap = habase + (size_t)p * 256;
            Ab[p][0] = __ldcg(ap);
            Ab[p][1] = __ldcg(ap + 1);
        }

#pragma unroll
        for (int s = 0; s < 16; s++) {
            if (s < 15) {
                const uint2* wp = wbase + (size_t)(s + 1) * 128;
#pragma unroll
                for (int g = 0; g < 4; g++) Bb[(s + 1) & 1][g] = __ldg(wp + g * 32);
            }
            if (s < 13) {
                const uint4* ap = habase + (size_t)(s + 3) * 256;
                Ab[(s + 3) & 3][0] = __ldcg(ap);
                Ab[(s + 3) & 3][1] = __ldcg(ap + 1);
            }
            uint4 A0 = Ab[s & 3][0];
            uint4 A1 = Ab[s & 3][1];
#pragma unroll
            for (int g = 0; g < 4; g++) {
                uint2 B = Bb[s & 1][g];
                MMA_F16(acc1[g], A0, B.x, B.y);
                MMA_F16(acc2[g], A1, B.x, B.y);
            }
        }

        // combine scaled-lo accumulator
        float gf[4][4];
#pragma unroll
        for (int g = 0; g < 4; g++)
#pragma unroll
            for (int c = 0; c < 4; c++)
                gf[g][c] = acc1[g][c] + acc2[g][c] * (1.0f / 2048.0f);

        // ===== psum handoff =====
        if (kh >= 1) {
#pragma unroll
            for (int g = 0; g < 4; g++)
#pragma unroll
                for (int c = 0; c < 4; c++)
                    psum[kh - 1][mt][g * 4 + c][lid] = gf[g][c];
        }
        __syncthreads();   // psum + xs(t) visible; orders xs[nb] WAR

        // ===== PHASE 4 =====
        if (kh == 0) {
            // hoisted xs reads
            float xr[2][4][2];
#pragma unroll
            for (int mh = 0; mh < 2; mh++)
#pragma unroll
                for (int g = 0; g < 4; g++)
#pragma unroll
                    for (int cbit = 0; cbit < 2; cbit++)
                        xr[mh][g][cbit] = xs[cb][r0 + 8 * mh][g * 8 + 2 * tig + cbit];

#pragma unroll
            for (int q = 0; q < 3; q++)
#pragma unroll
                for (int g = 0; g < 4; g++)
#pragma unroll
                    for (int c = 0; c < 4; c++)
                        gf[g][c] += psum[q][mt][g * 4 + c][lid];

            uint32_t* hb = g_hfrag[nb] + (((sj * 4 + mt) * 32 + lid) * 8);
#pragma unroll
            for (int mh = 0; mh < 2; mh++) {
                int row = r0 + 8 * mh;
                float h2[2];
#pragma unroll
                for (int cbit = 0; cbit < 2; cbit++) {
                    int ci = mh * 2 + cbit;
                    int ul = 2 * tig + cbit;
                    float ig = gf[0][ci] + xr[mh][0][cbit] + bhs[ul];
                    float fg = gf[1][ci] + xr[mh][1][cbit] + bhs[8 + ul];
                    float gg = gf[2][ci] + xr[mh][2][cbit] + bhs[16 + ul];
                    float og = gf[3][ci] + xr[mh][3][cbit] + bhs[24 + ul];
                    float cn = sigmf(fg) * creg[ci] + sigmf(ig) * tanhfast(gg);
                    creg[ci] = cn;
                    h2[cbit] = sigmf(og) * tanhfast(cn);
                }
                float hi0 = f16val(h2[0]);
                float hi1 = f16val(h2[1]);
                hb[regbase + mh]     = pack_f16x2(h2[0], h2[1]);
                hb[4 + regbase + mh] = pack_f16x2((h2[0] - hi0) * 2048.0f,
                                                  (h2[1] - hi1) * 2048.0f);
                if (t == SEQ - 1) {
                    *(float2*)(g_hfin + row * HID + j * 8 + 2 * tig) =
                        make_float2(h2[0], h2[1]);
                }
            }
            // epilogue warps only: order h stores, then publish arrival
            asm volatile("bar.sync 1, 128;" ::: "memory");
            if (tid == 0)
                asm volatile("red.release.gpu.global.add.u32 [%0], %1;"
                             :: "l"(&g_count), "r"(1u) : "memory");
        } else if (t + 1 < SEQ) {
            // shadow xproj for step t+1 (fills the epilogue/barrier window)
            int q = wid - 4;
            xproj_tile(t + 1, nb, j, q, lid, xs, bihs);
            if (wid < 8) xproj_tile(t + 1, nb, j, q + 12, lid, xs, bihs);
        }
    }
}

// ===================== head (parallel warp-reduce) =====================
__global__ void final_kernel(const float* __restrict__ W1,
                             const float* __restrict__ b1,
                             const float* __restrict__ W2,
                             const float* __restrict__ b2,
                             float* __restrict__ out) {
    __shared__ float hidden[64];
    const int b   = blockIdx.x;
    const int tid = threadIdx.x;
    const int wid = tid >> 5;
    const int lid = tid & 31;
    const float* hrow = g_hfin + b * HID;

#pragma unroll
    for (int q = 0; q < 8; q++) {
        int jj = wid + q * 8;
        const float* wrow = W1 + jj * HID;
        float s = 0.0f;
#pragma unroll 8
        for (int k = lid; k < HID; k += 32) s = fmaf(hrow[k], wrow[k], s);
#pragma unroll
        for (int o = 16; o; o >>= 1) s += __shfl_xor_sync(0xFFFFFFFFu, s, o);
        if (lid == 0) hidden[jj] = fmaxf(s + b1[jj], 0.0f) * W2[jj];
    }
    __syncthreads();
    if (wid == 0) {
        float v = hidden[lid] + hidden[lid + 32];
#pragma unroll
        for (int o = 16; o; o >>= 1) v += __shfl_xor_sync(0xFFFFFFFFu, v, o);
        if (lid == 0) out[b] = v + b2[0];
    }
}

// ===================== launch =====================
extern "C" void kernel_launch(void* const* d_in, const int* in_sizes, int n_in,
                              void* d_out, int out_size) {
    (void)in_sizes; (void)n_in; (void)out_size;
    const int*   x         = (const int*)  d_in[0];
    const float* emb_table = (const float*)d_in[2];
    const float* W_ih      = (const float*)d_in[3];
    const float* b_ih      = (const float*)d_in[4];
    const float* W_hh      = (const float*)d_in[5];
    const float* b_hh      = (const float*)d_in[6];
    const float* W1        = (const float*)d_in[7];
    const float* b1        = (const float*)d_in[8];
    const float* W2        = (const float*)d_in[9];
    const float* b2        = (const float*)d_in[10];
    float* out = (float*)d_out;

    init_kernel<<<1, 32>>>();
    wconv_kernel<<<(4096 * 512 + 255) / 256, 256>>>(W_hh);
    wihconv_kernel<<<(4096 * 256 + 255) / 256, 256>>>(W_ih);
    gather_kernel<<<2048, 256>>>(x, emb_table);
    lstm_persistent<<<NBLK, 512>>>(b_hh, b_ih);
    final_kernel<<<BATCH, 256>>>(W1, b1, W2, b2, out);
}

// round 17
// speedup vs baseline: 1.2141x; 1.2141x over previous
#include <cuda_runtime.h>
#include <cuda_fp16.h>
#include <math.h>
#include <stdint.h>

#define HID   1024
#define EMBD  512
#define BATCH 64
#define SEQ   512
#define G4    4096
#define NBLK  128

// ===================== device scratch =====================
// W_hh fp16, m16n8k16 B-fragment order (single plane):
//   u32 idx = (((jj*64 + s)*4 + g)*32 + lane)*2 + khalf
__device__ uint32_t g_wfrag16[128 * 64 * 4 * 32 * 2];      // 4 MB
// W_ih fp16 B-fragment order (single plane):
//   u32 idx = ((ntile*32 + s)*32 + lane)*2 + khalf
__device__ uint32_t g_wihfrag[512 * 32 * 32 * 2];          // 4 MB
// emb rows in A-fragment order, fp16 single plane:
//   uint4 idx = (mtile*32 + s)*32 + lane
__device__ uint4    g_afrag[2048 * 32 * 32];               // 33 MB
// h in A-fragment order, fp16: part0 = hi, part1 = (h-hi)*2048; double buffered
__device__ uint32_t g_hfrag[2][64 * 4 * 32 * 8];           // 512 KB x2
__device__ float    g_hfin[BATCH * HID];
__device__ unsigned g_count;

__global__ void init_kernel() {
    if (blockIdx.x == 0 && threadIdx.x == 0) g_count = 0u;
}

// ===================== helpers =====================
// fast sigmoid: rcp(1 + 2^(-v*log2e)); abs error ~2^-22 (MUFU approx)
__device__ __forceinline__ float sigmf(float v) {
    float e, r;
    asm("ex2.approx.f32 %0, %1;" : "=f"(e) : "f"(-v * 1.4426950408889634f));
    asm("rcp.approx.f32 %0, %1;" : "=f"(r) : "f"(1.0f + e));
    return r;
}
// fast tanh: 1 - 2*rcp(2^(2x*log2e) + 1); abs error ~2^-22
__device__ __forceinline__ float tanhfast(float x) {
    float e, r;
    asm("ex2.approx.f32 %0, %1;" : "=f"(e) : "f"(x * 2.8853900817779268f));
    asm("rcp.approx.f32 %0, %1;" : "=f"(r) : "f"(e + 1.0f));
    return 1.0f - 2.0f * r;
}

__device__ __forceinline__ uint32_t pack_f16x2(float e0, float e1) {
    __half2 h = __floats2half2_rn(e0, e1);
    return *(uint32_t*)&h;
}
__device__ __forceinline__ float f16val(float v) {
    return __half2float(__float2half_rn(v));
}

#define MMA_F16(d, a, b0, b1) \
    asm volatile("mma.sync.aligned.m16n8k16.row.col.f32.f16.f16.f32 " \
        "{%0,%1,%2,%3}, {%4,%5,%6,%7}, {%8,%9}, {%0,%1,%2,%3};" \
        : "+f"((d)[0]), "+f"((d)[1]), "+f"((d)[2]), "+f"((d)[3]) \
        : "r"((a).x), "r"((a).y), "r"((a).z), "r"((a).w), "r"(b0), "r"(b1))

// ===================== W_hh -> fp16 fragment converter =====================
__global__ void wconv_kernel(const float* __restrict__ W_hh) {
    int id = blockIdx.x * blockDim.x + threadIdx.x;   // 4096*512 (n, k-pair)
    if (id >= 4096 * 512) return;
    int n  = id >> 9;
    int k  = (id & 511) * 2;
    float2 w = *(const float2*)(W_hh + (size_t)n * HID + k);

    int g  = n >> 10, jj = (n >> 3) & 127, ul = n & 7;
    int s  = k >> 4, tig = (k >> 1) & 3, khalf = (k >> 3) & 1;
    int lane = (ul << 2) | tig;
    uint32_t base = (uint32_t)((((jj * 64 + s) * 4 + g) * 32 + lane) * 2 + khalf);
    g_wfrag16[base] = pack_f16x2(w.x, w.y);
}

// ===================== W_ih -> fp16 fragment converter =====================
__global__ void wihconv_kernel(const float* __restrict__ W_ih) {
    int id = blockIdx.x * blockDim.x + threadIdx.x;   // 4096*256 k-pairs
    if (id >= 4096 * 256) return;
    int n  = id >> 8;
    int k  = (id & 255) * 2;
    float2 w = *(const float2*)(W_ih + (size_t)n * EMBD + k);

    int ntile = n >> 3, ul = n & 7;
    int s = k >> 4, tig = (k >> 1) & 3, khalf = (k >> 3) & 1;
    int lane = (ul << 2) | tig;
    uint32_t base = (uint32_t)(((ntile * 32 + s) * 32 + lane) * 2 + khalf);
    g_wihfrag[base] = pack_f16x2(w.x, w.y);
}

// ===================== embedding gather -> fp16 A fragments (1 plane) ==========
__global__ void gather_kernel(const int*   __restrict__ x,
                              const float* __restrict__ emb_table) {
    __shared__ int toks[16];
    const int mtile = blockIdx.x;
    const int tid = threadIdx.x;
    const int wid = tid >> 5;
    const int lid = tid & 31;

    if (tid < 16) {
        int m = mtile * 16 + tid;
        int t = m >> 6, b = m & 63;
        toks[tid] = x[b * SEQ + t];
    }
    __syncthreads();

    const int r0 = lid >> 2;
    const int c0 = (lid & 3) * 2;
    const int tok0 = toks[r0];
    const int tok1 = toks[r0 + 8];
    const float* e0 = emb_table + (size_t)tok0 * EMBD;
    const float* e1 = emb_table + (size_t)tok1 * EMBD;

#pragma unroll
    for (int q = 0; q < 4; q++) {
        int s = wid * 4 + q;
        int kb = s * 16;
        float2 v00 = (tok0 == 0) ? make_float2(0.f, 0.f) : *(const float2*)(e0 + kb + c0);
        float2 v01 = (tok0 == 0) ? make_float2(0.f, 0.f) : *(const float2*)(e0 + kb + c0 + 8);
        float2 v10 = (tok1 == 0) ? make_float2(0.f, 0.f) : *(const float2*)(e1 + kb + c0);
        float2 v11 = (tok1 == 0) ? make_float2(0.f, 0.f) : *(const float2*)(e1 + kb + c0 + 8);

        uint4 hi;
        hi.x = pack_f16x2(v00.x, v00.y);
        hi.y = pack_f16x2(v10.x, v10.y);
        hi.z = pack_f16x2(v01.x, v01.y);
        hi.w = pack_f16x2(v11.x, v11.y);

        g_afrag[((size_t)mtile * 32 + s) * 32 + lid] = hi;
    }
}

// ===================== grid barrier primitives =====================
__device__ __forceinline__ void grid_bar_full(unsigned target) {
    __syncthreads();
    if (threadIdx.x == 0) {
        asm volatile("red.release.gpu.global.add.u32 [%0], %1;"
                     :: "l"(&g_count), "r"(1u) : "memory");
        unsigned v;
        while (true) {
            asm volatile("ld.acquire.gpu.global.u32 %0, [%1];"
                         : "=r"(v) : "l"(&g_count) : "memory");
            if (v >= target * NBLK) break;
            __nanosleep(16);
        }
    }
    __syncthreads();
}

// ===================== fused x_proj warp-tile (round-13 mapping, 2 acc chains) ===
// Tile q = gate*4 + mtile: computes xs[buf][mtile*16 + a][gate*8 + ul]
//   = emb(t=tt) . W_ih + b_ih for this block's 8 columns of gate `gate`.
__device__ __forceinline__ void xproj_tile(int tt, int buf, int j, int q,
                                           int lid, float xs[2][64][36],
                                           const float* bihs) {
    const int g   = q >> 2;
    const int mtl = q & 3;
    const uint4* ab = g_afrag + ((size_t)(tt * 4 + mtl) * 32) * 32 + lid;
    const uint2* bb = ((const uint2*)g_wihfrag)
                    + ((size_t)(g * 128 + j) * 32) * 32 + lid;
    float axa[4] = {0.f, 0.f, 0.f, 0.f};
    float axb[4] = {0.f, 0.f, 0.f, 0.f};
    uint4 Ar[4];
    uint2 Br[4];
#pragma unroll
    for (int p = 0; p < 3; p++) {
        Ar[p] = __ldg(ab + (size_t)p * 32);
        Br[p] = __ldg(bb + (size_t)p * 32);
    }
#pragma unroll
    for (int s = 0; s < 32; s++) {
        if (s < 29) {
            Ar[(s + 3) & 3] = __ldg(ab + (size_t)(s + 3) * 32);
            Br[(s + 3) & 3] = __ldg(bb + (size_t)(s + 3) * 32);
        }
        if (s & 1) { MMA_F16(axb, Ar[s & 3], Br[s & 3].x, Br[s & 3].y); }
        else       { MMA_F16(axa, Ar[s & 3], Br[s & 3].x, Br[s & 3].y); }
    }
    int a = lid >> 2, bq = lid & 3;
    int colb = g * 8 + bq * 2;
    float bi0 = bihs[colb], bi1 = bihs[colb + 1];
    *(float2*)&xs[buf][mtl * 16 + a][colb] =
        make_float2(axa[0] + axb[0] + bi0, axa[1] + axb[1] + bi1);
    *(float2*)&xs[buf][mtl * 16 + a + 8][colb] =
        make_float2(axa[2] + axb[2] + bi0, axa[3] + axb[3] + bi1);
}

// ===================== persistent LSTM recurrence + balanced shadow xproj =======
// Warp wid = kh*4 + mt. Each warp owns ONE xproj tile per step:
//   warps 4-15: tile wid-4 (computed right after psum sync, in the epilogue window)
//   warps 0-3:  tile 12+wid (computed after arrive, during their barrier idle-wait)
__global__ void __launch_bounds__(512, 1)
lstm_persistent(const float* __restrict__ b_hh, const float* __restrict__ b_ih) {
    __shared__ float xs[2][64][36];
    __shared__ float psum[3][4][16][32];
    __shared__ float bhs[32];
    __shared__ float bihs[32];

    const int j   = blockIdx.x;
    const int tid = threadIdx.x;
    const int wid = tid >> 5;
    const int lid = tid & 31;
    const int kh  = wid >> 2;              // K-quarter 0..3
    const int mt  = wid & 3;               // m-tile
    const int r0  = mt * 16 + (lid >> 2);
    const int tig = lid & 3;
    const int sj  = j >> 1;
    const int regbase = (j & 1) << 1;
    const int myq = (wid >= 4) ? (wid - 4) : (12 + wid);   // xproj tile id

    if (tid < 32) {
        int g = tid >> 3, ul = tid & 7;
        bhs[tid]  = b_hh[g * HID + j * 8 + ul];
        bihs[tid] = b_ih[g * HID + j * 8 + ul];
    }

    if (wid < 4) {
        uint32_t* hb = g_hfrag[0] + (((sj * 4 + wid) * 32 + lid) * 8);
#pragma unroll
        for (int mh = 0; mh < 2; mh++) {
            hb[regbase + mh]     = 0u;
            hb[4 + regbase + mh] = 0u;
        }
    }
    float creg[4];
#pragma unroll
    for (int q = 0; q < 4; q++) creg[q] = 0.0f;

    __syncthreads();           // bihs visible for prologue
    // prologue: x_proj[0] -> xs[0]; every warp computes its own tile
    xproj_tile(0, 0, j, myq, lid, xs, bihs);

    grid_bar_full(1);          // h zeroed + xs[0] ready everywhere; counter = NBLK

    // B-fragment base for this warp's K-quarter (uint2; per-s stride 128, per-g 32)
    const uint2* wbase = ((const uint2*)g_wfrag16)
                       + ((size_t)j * 64 + kh * 16) * 128 + lid;

    for (int t = 0; t < SEQ; t++) {
        const int cb = t & 1, nb = cb ^ 1;

        // ===== PHASE 1: B prefetch (h-independent) =====
        uint2 Bb[2][4];
#pragma unroll
        for (int g = 0; g < 4; g++) Bb[0][g] = __ldg(wbase + g * 32);

        // ===== PHASE 2: wait for all blocks' h writes of step t-1 =====
        if (tid == 0) {
            const unsigned tgt = (unsigned)(t + 1) * NBLK;
            unsigned v;
            while (true) {
                asm volatile("ld.acquire.gpu.global.u32 %0, [%1];"
                             : "=r"(v) : "l"(&g_count) : "memory");
                if (v >= tgt) break;
                __nanosleep(16);
            }
        }
        __syncthreads();

        // ===== PHASE 3: K-quarter MMA loop (16 k-steps, 2 mma per g) =====
        const uint4* habase = ((const uint4*)g_hfrag[cb])
                            + ((size_t)(kh * 64 + mt)) * 64 + lid * 2;
        uint4 Ab[4][2];       // ring, fill distance 3
        float acc1[4][4], acc2[4][4];
#pragma unroll
        for (int g = 0; g < 4; g++)
#pragma unroll
            for (int c = 0; c < 4; c++) { acc1[g][c] = 0.0f; acc2[g][c] = 0.0f; }

#pragma unroll
        for (int p = 0; p < 3; p++) {
            const uint4* ap = habase + (size_t)p * 256;
            Ab[p][0] = __ldcg(ap);
            Ab[p][1] = __ldcg(ap + 1);
        }

#pragma unroll
        for (int s = 0; s < 16; s++) {
            if (s < 15) {
                const uint2* wp = wbase + (size_t)(s + 1) * 128;
#pragma unroll
                for (int g = 0; g < 4; g++) Bb[(s + 1) & 1][g] = __ldg(wp + g * 32);
            }
            if (s < 13) {
                const uint4* ap = habase + (size_t)(s + 3) * 256;
                Ab[(s + 3) & 3][0] = __ldcg(ap);
                Ab[(s + 3) & 3][1] = __ldcg(ap + 1);
            }
            uint4 A0 = Ab[s & 3][0];
            uint4 A1 = Ab[s & 3][1];
#pragma unroll
            for (int g = 0; g < 4; g++) {
                uint2 B = Bb[s & 1][g];
                MMA_F16(acc1[g], A0, B.x, B.y);
                MMA_F16(acc2[g], A1, B.x, B.y);
            }
        }

        // combine scaled-lo accumulator
        float gf[4][4];
#pragma unroll
        for (int g = 0; g < 4; g++)
#pragma unroll
            for (int c = 0; c < 4; c++)
                gf[g][c] = acc1[g][c] + acc2[g][c] * (1.0f / 2048.0f);

        // ===== psum handoff =====
        if (kh >= 1) {
#pragma unroll
            for (int g = 0; g < 4; g++)
#pragma unroll
                for (int c = 0; c < 4; c++)
                    psum[kh - 1][mt][g * 4 + c][lid] = gf[g][c];
        }
        __syncthreads();   // psum + xs(t) visible; orders xs[nb] WAR

        // ===== PHASE 4 =====
        if (kh == 0) {
            // hoisted xs reads
            float xr[2][4][2];
#pragma unroll
            for (int mh = 0; mh < 2; mh++)
#pragma unroll
                for (int g = 0; g < 4; g++)
#pragma unroll
                    for (int cbit = 0; cbit < 2; cbit++)
                        xr[mh][g][cbit] = xs[cb][r0 + 8 * mh][g * 8 + 2 * tig + cbit];

#pragma unroll
            for (int q = 0; q < 3; q++)
#pragma unroll
                for (int g = 0; g < 4; g++)
#pragma unroll
                    for (int c = 0; c < 4; c++)
                        gf[g][c] += psum[q][mt][g * 4 + c][lid];

            uint32_t* hb = g_hfrag[nb] + (((sj * 4 + mt) * 32 + lid) * 8);
#pragma unroll
            for (int mh = 0; mh < 2; mh++) {
                int row = r0 + 8 * mh;
                float h2[2];
#pragma unroll
                for (int cbit = 0; cbit < 2; cbit++) {
                    int ci = mh * 2 + cbit;
                    int ul = 2 * tig + cbit;
                    float ig = gf[0][ci] + xr[mh][0][cbit] + bhs[ul];
                    float fg = gf[1][ci] + xr[mh][1][cbit] + bhs[8 + ul];
                    float gg = gf[2][ci] + xr[mh][2][cbit] + bhs[16 + ul];
                    float og = gf[3][ci] + xr[mh][3][cbit] + bhs[24 + ul];
                    float cn = sigmf(fg) * creg[ci] + sigmf(ig) * tanhfast(gg);
                    creg[ci] = cn;
                    h2[cbit] = sigmf(og) * tanhfast(cn);
                }
                float hi0 = f16val(h2[0]);
                float hi1 = f16val(h2[1]);
                hb[regbase + mh]     = pack_f16x2(h2[0], h2[1]);
                hb[4 + regbase + mh] = pack_f16x2((h2[0] - hi0) * 2048.0f,
                                                  (h2[1] - hi1) * 2048.0f);
                if (t == SEQ - 1) {
                    *(float2*)(g_hfin + row * HID + j * 8 + 2 * tig) =
                        make_float2(h2[0], h2[1]);
                }
            }
            // epilogue warps: order h stores, publish arrival, THEN shadow tile
            asm volatile("bar.sync 1, 128;" ::: "memory");
            if (tid == 0)
                asm volatile("red.release.gpu.global.add.u32 [%0], %1;"
                             :: "l"(&g_count), "r"(1u) : "memory");
            if (t + 1 < SEQ)
                xproj_tile(t + 1, nb, j, myq, lid, xs, bihs);
        } else if (t + 1 < SEQ) {
            // run-ahead warps: shadow tile fills the epilogue/barrier window
            xproj_tile(t + 1, nb, j, myq, lid, xs, bihs);
        }
    }
}

// ===================== head (parallel warp-reduce) =====================
__global__ void final_kernel(const float* __restrict__ W1,
                             const float* __restrict__ b1,
                             const float* __restrict__ W2,
                             const float* __restrict__ b2,
                             float* __restrict__ out) {
    __shared__ float hidden[64];
    const int b   = blockIdx.x;
    const int tid = threadIdx.x;
    const int wid = tid >> 5;
    const int lid = tid & 31;
    const float* hrow = g_hfin + b * HID;

#pragma unroll
    for (int q = 0; q < 8; q++) {
        int jj = wid + q * 8;
        const float* wrow = W1 + jj * HID;
        float s = 0.0f;
#pragma unroll 8
        for (int k = lid; k < HID; k += 32) s = fmaf(hrow[k], wrow[k], s);
#pragma unroll
        for (int o = 16; o; o >>= 1) s += __shfl_xor_sync(0xFFFFFFFFu, s, o);
        if (lid == 0) hidden[jj] = fmaxf(s + b1[jj], 0.0f) * W2[jj];
    }
    __syncthreads();
    if (wid == 0) {
        float v = hidden[lid] + hidden[lid + 32];
#pragma unroll
        for (int o = 16; o; o >>= 1) v += __shfl_xor_sync(0xFFFFFFFFu, v, o);
        if (lid == 0) out[b] = v + b2[0];
    }
}

// ===================== launch =====================
extern "C" void kernel_launch(void* const* d_in, const int* in_sizes, int n_in,
                              void* d_out, int out_size) {
    (void)in_sizes; (void)n_in; (void)out_size;
    const int*   x         = (const int*)  d_in[0];
    const float* emb_table = (const float*)d_in[2];
    const float* W_ih      = (const float*)d_in[3];
    const float* b_ih      = (const float*)d_in[4];
    const float* W_hh      = (const float*)d_in[5];
    const float* b_hh      = (const float*)d_in[6];
    const float* W1        = (const float*)d_in[7];
    const float* b1        = (const float*)d_in[8];
    const float* W2        = (const float*)d_in[9];
    const float* b2        = (const float*)d_in[10];
    float* out = (float*)d_out;

    init_kernel<<<1, 32>>>();
    wconv_kernel<<<(4096 * 512 + 255) / 256, 256>>>(W_hh);
    wihconv_kernel<<<(4096 * 256 + 255) / 256, 256>>>(W_ih);
    gather_kernel<<<2048, 256>>>(x, emb_table);
    lstm_persistent<<<NBLK, 512>>>(b_hh, b_ih);
    final_kernel<<<BATCH, 256>>>(W1, b1, W2, b2, out);
}